// round 14
// baseline (speedup 1.0000x reference)
#include <cuda_runtime.h>
#include <cuda_bf16.h>
#include <cuda_fp8.h>
#include <stdint.h>

#define ATOMS   4096
#define DMODEL  16384
#define BATCH   32
#define ITERS   10
#define TEMP    0.001f

#define KCHUNKS 16
#define KCHUNK  (DMODEL / KCHUNKS)   // 1024
#define ATILE   128
#define NTILES  (ATOMS / ATILE)      // 32
#define KB      64                   // fp8 k elems per stage
#define NSTEPS  (KCHUNK / KB)        // 16
#define MAXC    64
#define WINDOW  0.40f

#define DSCALE  8192.0f
#define RSCALE  32.0f
#define INV_S   (1.0f / (DSCALE * RSCALE))

#define NRES    (BATCH * DMODEL)     // 524288
#define GRID_I  512                  // co-resident: 4/SM x 148 = 592
#define SLOTS   16

#define DSMEM_BYTES 49152            // 2x8KB dict stages + 32KB resid chunk

// ---------------- persistent scratch --------------------------------------
// dict fp8, tile-major: [kc][nt][stage][row(128)][64B], swizzled
__device__ uint8_t  g_dict_f8[(size_t)ATOMS * DMODEL];              // 64 MB
__device__ float    g_resid[(size_t)BATCH * DMODEL];                // 2 MB
// resid fp8, tile-major: [kc][row(32)][1024B], swizzled
__device__ uint8_t  g_resid_f8[(size_t)BATCH * DMODEL];             // 0.5 MB
__device__ float    g_part[(size_t)KCHUNKS * BATCH * ATOMS];        // 8 MB
__device__ unsigned g_rowmax[BATCH];
__device__ int      g_cnt[BATCH];
__device__ int      g_cand[BATCH * MAXC];
__device__ float    g_ex[BATCH * MAXC];
__device__ float    g_lpart[512];
__device__ unsigned g_bcnt[2];
__device__ unsigned g_bgen[2];

// ---------------- address helpers ------------------------------------------
__device__ __forceinline__ size_t dict8_addr(int a, int k) {
    const int kc = k >> 10, nt = a >> 7, s = (k >> 6) & 15, r = a & 127;
    const int seg = (k >> 4) & 3, byte = k & 15;
    const int sg = seg ^ ((r >> 1) & 3);
    return (((size_t)(kc * NTILES + nt) * 16 + s) << 13) + (r << 6) + (sg << 4) + byte;
}
__device__ __forceinline__ size_t resid8_addr(int r, int k) {
    const int kc = k >> 10;
    const int seg = (k & 1023) >> 4, byte = k & 15;
    const int sg = seg ^ (r & 7);
    return ((size_t)(kc * BATCH + r) << 10) + (sg << 4) + byte;
}

// ---------------- PTX helpers ----------------------------------------------
__device__ __forceinline__ uint32_t smem_u32(const void* p) {
    return (uint32_t)__cvta_generic_to_shared(p);
}
__device__ __forceinline__ void ldsm_x4(uint32_t* r, uint32_t addr) {
    asm volatile("ldmatrix.sync.aligned.m8n8.x4.shared.b16 {%0,%1,%2,%3}, [%4];\n"
        : "=r"(r[0]), "=r"(r[1]), "=r"(r[2]), "=r"(r[3]) : "r"(addr));
}
__device__ __forceinline__ void ldsm_x2(uint32_t* r, uint32_t addr) {
    asm volatile("ldmatrix.sync.aligned.m8n8.x2.shared.b16 {%0,%1}, [%2];\n"
        : "=r"(r[0]), "=r"(r[1]) : "r"(addr));
}
__device__ __forceinline__ void mma16832(float* c, const uint32_t* a, const uint32_t* b) {
    asm volatile(
        "mma.sync.aligned.m16n8k32.row.col.f32.e4m3.e4m3.f32 "
        "{%0,%1,%2,%3}, {%4,%5,%6,%7}, {%8,%9}, {%0,%1,%2,%3};\n"
        : "+f"(c[0]), "+f"(c[1]), "+f"(c[2]), "+f"(c[3])
        : "r"(a[0]), "r"(a[1]), "r"(a[2]), "r"(a[3]), "r"(b[0]), "r"(b[1]));
}
__device__ __forceinline__ uint32_t f8x4(float x, float y, float z, float w) {
    __nv_fp8x4_e4m3 p(make_float4(x, y, z, w));
    return *(uint32_t*)&p;
}
__device__ __forceinline__ unsigned fenc(float v) {
    int b = __float_as_int(v);
    return (b >= 0) ? ((unsigned)b | 0x80000000u) : ~(unsigned)b;
}
__device__ __forceinline__ float fdec(unsigned k) {
    int b = (k & 0x80000000u) ? (int)(k & 0x7fffffffu) : ~(int)k;
    return __int_as_float(b);
}
// mbarrier + bulk-copy (TMA-path) helpers
__device__ __forceinline__ void mbar_init1(uint32_t m) {
    asm volatile("mbarrier.init.shared.b64 [%0], 1;" :: "r"(m) : "memory");
}
__device__ __forceinline__ void mbar_expect(uint32_t m, uint32_t tx) {
    asm volatile("mbarrier.arrive.expect_tx.shared.b64 _, [%0], %1;"
        :: "r"(m), "r"(tx) : "memory");
}
__device__ __forceinline__ void bulkcp(uint32_t dst, const void* src, uint32_t sz, uint32_t m) {
    asm volatile("cp.async.bulk.shared::cta.global.mbarrier::complete_tx::bytes "
                 "[%0], [%1], %2, [%3];"
        :: "r"(dst), "l"(src), "r"(sz), "r"(m) : "memory");
}
__device__ __forceinline__ void mbar_wait(uint32_t m, uint32_t p) {
    uint32_t done;
    asm volatile("{\n.reg .pred P;\n"
        "mbarrier.try_wait.parity.acquire.cta.shared::cta.b64 P, [%1], %2;\n"
        "selp.b32 %0, 1, 0, P;\n}"
        : "=r"(done) : "r"(m), "r"(p) : "memory");
    while (!done) {
        asm volatile("{\n.reg .pred P;\n"
            "mbarrier.try_wait.parity.acquire.cta.shared::cta.b64 P, [%1], %2, 0x989680;\n"
            "selp.b32 %0, 1, 0, P;\n}"
            : "=r"(done) : "r"(m), "r"(p) : "memory");
    }
}
// Generation-counter grid barrier (no reset across launches/replays).
__device__ __forceinline__ void gbar(int b) {
    __syncthreads();
    if (threadIdx.x == 0) {
        volatile unsigned* gen = &g_bgen[b];
        const unsigned g = *gen;
        __threadfence();
        const unsigned o = atomicAdd(&g_bcnt[b], 1u);
        if (o == GRID_I - 1) {
            g_bcnt[b] = 0;
            __threadfence();
            atomicAdd(&g_bgen[b], 1u);
        } else {
            while (*gen == g) __nanosleep(64);
        }
        __threadfence();
    }
    __syncthreads();
}

// ---------------- kernels ---------------------------------------------------

// dict fp32 -> fp8 into tile-major swizzled layout.
__global__ void k_convert_dict(const float* __restrict__ dict) {
    const size_t i = (size_t)blockIdx.x * blockDim.x + threadIdx.x;  // 16M groups
    const int a = (int)(i >> 12);
    const int k = (int)(i & 4095) * 4;
    const float4 v = *(const float4*)(dict + (size_t)a * DMODEL + k);
    *(uint32_t*)(g_dict_f8 + dict8_addr(a, k)) =
        f8x4(v.x * DSCALE, v.y * DSCALE, v.z * DSCALE, v.w * DSCALE);
}

__global__ void k_init(const float* __restrict__ x) {
    const size_t i = (size_t)blockIdx.x * blockDim.x + threadIdx.x;  // 131072 groups
    const int r = (int)(i >> 12);
    const int k = (int)(i & 4095) * 4;
    const float4 v = *(const float4*)(x + (size_t)r * DMODEL + k);
    *(float4*)(g_resid + (size_t)r * DMODEL + k) = v;
    *(uint32_t*)(g_resid_f8 + resid8_addr(r, k)) =
        f8x4(v.x * RSCALE, v.y * RSCALE, v.z * RSCALE, v.w * RSCALE);
    if (blockIdx.x == 0 && threadIdx.x < BATCH) {
        g_rowmax[threadIdx.x] = 0u;
        g_cnt[threadIdx.x] = 0;
    }
}

// One MP iteration. Phase A uses bulk-copy (TMA path) loads.
// grid 512 x 256, dynamic smem 48KB (2x8KB dict stages + 32KB resid chunk).
__global__ void __launch_bounds__(256, 4) k_iter(const float* __restrict__ dict) {
    extern __shared__ uint8_t dsm[];
    uint8_t* sD = dsm;            // [2][8192]
    uint8_t* sR = dsm + 16384;    // [32][1024]
    __shared__ uint64_t mbarD[2], mbarR;
    __shared__ float sred[8];
    __shared__ int   s_n;
    __shared__ int   s_idx[MAXC];
    __shared__ float s_w[MAXC];

    const int t = threadIdx.x;
    const int lane = t & 31, warp = t >> 5;
    const int bx = blockIdx.x;
    const int nt = bx & (NTILES - 1);
    const int kc = bx >> 5;
    const int r = bx & (BATCH - 1);
    const int slot = kc;

    const uint32_t mD0 = smem_u32(&mbarD[0]);
    const uint32_t mD1 = smem_u32(&mbarD[1]);
    const uint32_t mR  = smem_u32(&mbarR);
    const uint32_t sDu = smem_u32(sD);
    const uint32_t sRu = smem_u32(sR);
    const uint8_t* dictBlock = g_dict_f8 + (((size_t)(kc * NTILES + nt)) << 17);

    if (t == 0) { mbar_init1(mD0); mbar_init1(mD1); mbar_init1(mR); }
    __syncthreads();
    if (t == 0) {
        mbar_expect(mR, 32768);
        bulkcp(sRu, g_resid_f8 + ((size_t)kc << 15), 32768, mR);
        mbar_expect(mD0, 8192);
        bulkcp(sDu, dictBlock, 8192, mD0);
        mbar_expect(mD1, 8192);
        bulkcp(sDu + 8192, dictBlock + 8192, 8192, mD1);
    }

    // ================= Phase A: fp8 tensor-core scores =================
    {
        float c0[2][4] = {{0.f,0.f,0.f,0.f},{0.f,0.f,0.f,0.f}};
        float c1[2][4] = {{0.f,0.f,0.f,0.f},{0.f,0.f,0.f,0.f}};

        const int rowA0 = lane & 15;
        const int rowA1 = rowA0 + 16;
        const int aseg  = (lane & 16) ? 1 : 0;
        const int rB0 = warp * 16 + (lane & 7);
        const int rB1 = rB0 + 8;
        const int bseg = (lane & 8) ? 1 : 0;

        for (int s = 0; s < NSTEPS; s++) {
            const int b = s & 1;
            mbar_wait(b ? mD1 : mD0, (s >> 1) & 1);
            if (s == 0) mbar_wait(mR, 0);

            #pragma unroll
            for (int ks = 0; ks < 2; ks++) {
                uint32_t a0[4], a1[4], b0v[2], b1v[2];
                const int segA = s * 4 + ks * 2 + aseg;
                ldsm_x4(a0, sRu + (rowA0 << 10) + (((segA ^ (rowA0 & 7)) & 63) << 4));
                ldsm_x4(a1, sRu + (rowA1 << 10) + (((segA ^ (rowA1 & 7)) & 63) << 4));
                const int segB = ks * 2 + bseg;
                ldsm_x2(b0v, sDu + (b << 13) + (rB0 << 6) + ((segB ^ ((rB0 >> 1) & 3)) << 4));
                ldsm_x2(b1v, sDu + (b << 13) + (rB1 << 6) + ((segB ^ ((rB1 >> 1) & 3)) << 4));
                mma16832(c0[0], a0, b0v);
                mma16832(c0[1], a1, b0v);
                mma16832(c1[0], a0, b1v);
                mma16832(c1[1], a1, b1v);
            }
            __syncthreads();
            if (t == 0 && s + 2 < NSTEPS) {
                const uint32_t m = ((s + 2) & 1) ? mD1 : mD0;
                mbar_expect(m, 8192);
                bulkcp(sDu + (((s + 2) & 1) << 13), dictBlock + ((size_t)(s + 2) << 13), 8192, m);
            }
        }

        const int gr = lane >> 2;
        float* P = g_part + (size_t)kc * BATCH * ATOMS;
        #pragma unroll
        for (int beta = 0; beta < 2; beta++) {
            const int ac = nt * ATILE + warp * 16 + beta * 8 + (lane & 3) * 2;
            const float (*c)[4] = beta ? c1 : c0;
            #pragma unroll
            for (int h = 0; h < 2; h++) {
                P[(size_t)(gr + h * 16 + 0) * ATOMS + ac]     = c[h][0];
                P[(size_t)(gr + h * 16 + 0) * ATOMS + ac + 1] = c[h][1];
                P[(size_t)(gr + h * 16 + 8) * ATOMS + ac]     = c[h][2];
                P[(size_t)(gr + h * 16 + 8) * ATOMS + ac + 1] = c[h][3];
            }
        }
    }

    gbar(0);   // all partials final

    // ====== Phase B: reduce slice + row max + select ====================
    const int myAtom = slot * 256 + t;
    float myScore;
    {
        float s = 0.f;
        #pragma unroll
        for (int c = 0; c < KCHUNKS; c++)
            s += g_part[((size_t)c * BATCH + r) * ATOMS + myAtom];
        myScore = s * INV_S;
    }
    {
        float lmax = myScore;
        #pragma unroll
        for (int o = 16; o > 0; o >>= 1) lmax = fmaxf(lmax, __shfl_xor_sync(0xffffffffu, lmax, o));
        if (lane == 0) sred[warp] = lmax;
        __syncthreads();
        if (t == 0) {
            float mm = sred[0];
            #pragma unroll
            for (int i = 1; i < 8; i++) mm = fmaxf(mm, sred[i]);
            atomicMax(&g_rowmax[r], fenc(mm));
        }
    }

    gbar(1);   // row maxes final

    {
        const float thr = fdec(g_rowmax[r]) - WINDOW;
        if (myScore > thr) {
            int p = atomicAdd(&g_cnt[r], 1);
            if (p < MAXC) g_cand[r * MAXC + p] = myAtom;
        }
    }

    gbar(0);   // candidate lists complete

    // ====== Phase C: sort (identical per row) + exact fp32 rescore ======
    if (t == 0) {
        int n = min(g_cnt[r], MAXC);
        for (int i = 0; i < n; i++) s_idx[i] = g_cand[r * MAXC + i];
        for (int i = 1; i < n; i++) {
            int v = s_idx[i], j = i - 1;
            while (j >= 0 && s_idx[j] > v) { s_idx[j + 1] = s_idx[j]; j--; }
            s_idx[j + 1] = v;
        }
        s_n = n;
    }
    __syncthreads();
    const int n = s_n;

    {
        const float* R = g_resid + (size_t)r * DMODEL;
        for (int j = slot; j < n; j += SLOTS) {
            const float* D = dict + (size_t)s_idx[j] * DMODEL;
            float acc = 0.f;
            #pragma unroll 4
            for (int d = t * 4; d < DMODEL; d += 1024) {
                const float4 rv = *(const float4*)(R + d);
                const float4 dv = *(const float4*)(D + d);
                acc += rv.x * dv.x + rv.y * dv.y + rv.z * dv.z + rv.w * dv.w;
            }
            #pragma unroll
            for (int o = 16; o > 0; o >>= 1) acc += __shfl_xor_sync(0xffffffffu, acc, o);
            if (lane == 0) sred[warp] = acc;
            __syncthreads();
            if (t == 0) {
                float s = 0.f;
                #pragma unroll
                for (int i = 0; i < 8; i++) s += sred[i];
                g_ex[r * MAXC + j] = s;
            }
            __syncthreads();
        }
    }

    gbar(1);   // exact scores final

    // ================= Phase D: softmax + apply ========================
    if (t == 0) {
        float em = -1e30f;
        for (int j = 0; j < n; j++) em = fmaxf(em, g_ex[r * MAXC + j]);
        float den = 0.f;
        for (int j = 0; j < n; j++) {
            const float wv = expf((g_ex[r * MAXC + j] - em) / TEMP);
            s_w[j] = wv; den += wv;
        }
        const float inv = 1.f / den;
        for (int j = 0; j < n; j++) s_w[j] *= inv;
    }
    __syncthreads();

    {
        const int col = slot * 1024 + t * 4;
        const size_t base = (size_t)r * DMODEL + col;
        float4 v = *(const float4*)(g_resid + base);
        for (int j = 0; j < n; j++) {
            const float wj = s_w[j];
            const float4 dv = *(const float4*)(dict + (size_t)s_idx[j] * DMODEL + col);
            v.x -= wj * dv.x; v.y -= wj * dv.y; v.z -= wj * dv.z; v.w -= wj * dv.w;
        }
        *(float4*)(g_resid + base) = v;
        // tiled+swizzled fp8 mirror
        const int sg = (t >> 2) ^ (r & 7);
        *(uint32_t*)(g_resid_f8 + (((size_t)(slot * BATCH + r)) << 10) + (sg << 4) + ((t & 3) << 2)) =
            f8x4(v.x * RSCALE, v.y * RSCALE, v.z * RSCALE, v.w * RSCALE);
    }

    if (slot == 0 && t == 0) {
        g_cnt[r] = 0;
        g_rowmax[r] = 0u;
    }
}

// Fused epilogue: copy residual to out AND per-block square-sums.
__global__ void k_epilogue(float* out, int out_size) {
    __shared__ float s[256];
    const int b = blockIdx.x, t = threadIdx.x;
    const int off = (out_size > NRES) ? 1 : 0;
    const size_t base = (size_t)b * 1024;
    float acc = 0.f;
    #pragma unroll
    for (int i = 0; i < 4; i++) {
        const size_t idx = base + t + i * 256;
        const float v = g_resid[idx];
        out[off + idx] = v;
        acc += v * v;
    }
    s[t] = acc; __syncthreads();
    for (int o = 128; o > 0; o >>= 1) { if (t < o) s[t] += s[t + o]; __syncthreads(); }
    if (t == 0) g_lpart[b] = s[0];
}

__global__ void k_finalize(float* out, int out_size) {
    __shared__ float s[512];
    const int t = threadIdx.x;
    s[t] = g_lpart[t]; __syncthreads();
    for (int o = 256; o > 0; o >>= 1) { if (t < o) s[t] += s[t + o]; __syncthreads(); }
    if (t == 0 && out_size > NRES) out[0] = s[0] / (float)NRES;
}

// ---------------- launch ----------------------------------------------------
extern "C" void kernel_launch(void* const* d_in, const int* in_sizes, int n_in,
                              void* d_out, int out_size) {
    const float* x = nullptr;
    const float* dict = nullptr;
    for (int i = 0; i < n_in; i++) {
        if (in_sizes[i] == NRES) x = (const float*)d_in[i];
        else if (in_sizes[i] == ATOMS * DMODEL) dict = (const float*)d_in[i];
    }
    float* out = (float*)d_out;

    // Opt-in for 48KB dynamic + static smem headroom (deterministic, host-side
    // attribute set; not a stream op, not an allocation — capture-legal).
    cudaFuncSetAttribute(k_iter, cudaFuncAttributeMaxDynamicSharedMemorySize, 57344);

    k_convert_dict<<<65536, 256>>>(dict);
    k_init<<<512, 256>>>(x);

    for (int it = 0; it < ITERS; it++)
        k_iter<<<GRID_I, 256, DSMEM_BYTES>>>(dict);

    k_epilogue<<<512, 256>>>(out, out_size);
    k_finalize<<<1, 512>>>(out, out_size);
}

// round 16
// speedup vs baseline: 1.0278x; 1.0278x over previous
#include <cuda_runtime.h>
#include <cuda_bf16.h>
#include <cuda_fp8.h>
#include <stdint.h>

#define ATOMS   4096
#define DMODEL  16384
#define BATCH   32
#define ITERS   10
#define TEMP    0.001f

#define KCHUNKS 16
#define KCHUNK  (DMODEL / KCHUNKS)   // 1024
#define ATILE   128
#define NTILES  (ATOMS / ATILE)      // 32
#define KB      64                   // fp8 k elems per stage
#define NSTAGE  4
#define NSTEPS  (KCHUNK / KB)        // 16
#define MAXC    96
#define WINDOW  0.40f

#define DSCALE  8192.0f
#define RSCALE  32.0f
#define INV_S   (1.0f / (DSCALE * RSCALE))

#define SROW    (KB + 16)            // 80 (pad: conflict-free ldsm)
#define NRES    (BATCH * DMODEL)     // 524288
#define GRID_I  512                  // co-resident: 4/SM x 148 = 592
#define SLOTS   16

#define SD_STAGE (ATILE * SROW)              // 10240
#define SR_STAGE (BATCH * SROW)              // 2560
#define DSMEM_BYTES (NSTAGE * (SD_STAGE + SR_STAGE))   // 51200

// ---------------- persistent scratch --------------------------------------
__device__ uint8_t  g_dict_f8[(size_t)ATOMS * DMODEL];              // 64 MB
__device__ float    g_resid[(size_t)BATCH * DMODEL];                // 2 MB
__device__ uint8_t  g_resid_f8[(size_t)BATCH * DMODEL];             // 0.5 MB
__device__ float    g_part[(size_t)KCHUNKS * BATCH * ATOMS];        // 8 MB
__device__ unsigned g_rowmax[BATCH];
__device__ int      g_cnt[BATCH];
__device__ int      g_cand[BATCH * MAXC];
__device__ float    g_csc[BATCH * MAXC];
__device__ float    g_ex[BATCH * MAXC];
__device__ float    g_lpart[512];
__device__ unsigned g_bcnt[1];
__device__ unsigned g_bgen[1];
__device__ unsigned g_rbc[BATCH * 2];
__device__ unsigned g_rbg[BATCH * 2];

// ---------------- PTX helpers ----------------------------------------------
__device__ __forceinline__ uint32_t smem_u32(const void* p) {
    return (uint32_t)__cvta_generic_to_shared(p);
}
__device__ __forceinline__ void cpa16(uint32_t s, const void* g) {
    asm volatile("cp.async.cg.shared.global [%0], [%1], 16;\n" :: "r"(s), "l"(g));
}
__device__ __forceinline__ void cpa_commit() {
    asm volatile("cp.async.commit_group;\n");
}
__device__ __forceinline__ void cpa_wait3() {
    asm volatile("cp.async.wait_group 3;\n");
}
__device__ __forceinline__ void cpa_wait0() {
    asm volatile("cp.async.wait_group 0;\n");
}
__device__ __forceinline__ void ldsm_x4(uint32_t* r, uint32_t addr) {
    asm volatile("ldmatrix.sync.aligned.m8n8.x4.shared.b16 {%0,%1,%2,%3}, [%4];\n"
        : "=r"(r[0]), "=r"(r[1]), "=r"(r[2]), "=r"(r[3]) : "r"(addr));
}
__device__ __forceinline__ void ldsm_x2(uint32_t* r, uint32_t addr) {
    asm volatile("ldmatrix.sync.aligned.m8n8.x2.shared.b16 {%0,%1}, [%2];\n"
        : "=r"(r[0]), "=r"(r[1]) : "r"(addr));
}
__device__ __forceinline__ void mma16832(float* c, const uint32_t* a, const uint32_t* b) {
    asm volatile(
        "mma.sync.aligned.m16n8k32.row.col.f32.e4m3.e4m3.f32 "
        "{%0,%1,%2,%3}, {%4,%5,%6,%7}, {%8,%9}, {%0,%1,%2,%3};\n"
        : "+f"(c[0]), "+f"(c[1]), "+f"(c[2]), "+f"(c[3])
        : "r"(a[0]), "r"(a[1]), "r"(a[2]), "r"(a[3]), "r"(b[0]), "r"(b[1]));
}
__device__ __forceinline__ uint32_t f8x4(float x, float y, float z, float w) {
    __nv_fp8x4_e4m3 p(make_float4(x, y, z, w));
    return *(uint32_t*)&p;
}
__device__ __forceinline__ unsigned fenc(float v) {
    int b = __float_as_int(v);
    return (b >= 0) ? ((unsigned)b | 0x80000000u) : ~(unsigned)b;
}
__device__ __forceinline__ float fdec(unsigned k) {
    int b = (k & 0x80000000u) ? (int)(k & 0x7fffffffu) : ~(int)k;
    return __int_as_float(b);
}
// full-grid generation barrier (512 CTAs)
__device__ __forceinline__ void gbar() {
    __syncthreads();
    if (threadIdx.x == 0) {
        volatile unsigned* gen = &g_bgen[0];
        const unsigned g = *gen;
        __threadfence();
        const unsigned o = atomicAdd(&g_bcnt[0], 1u);
        if (o == GRID_I - 1) {
            g_bcnt[0] = 0;
            __threadfence();
            atomicAdd(&g_bgen[0], 1u);
        } else {
            while (*gen == g) __nanosleep(64);
        }
        __threadfence();
    }
    __syncthreads();
}
// row-local generation barrier (the 16 slot-CTAs of one row)
__device__ __forceinline__ void rowbar(int r, int b) {
    __syncthreads();
    if (threadIdx.x == 0) {
        const int idx = r * 2 + b;
        volatile unsigned* gen = &g_rbg[idx];
        const unsigned g = *gen;
        __threadfence();
        const unsigned o = atomicAdd(&g_rbc[idx], 1u);
        if (o == SLOTS - 1) {
            g_rbc[idx] = 0;
            __threadfence();
            atomicAdd(&g_rbg[idx], 1u);
        } else {
            while (*gen == g) __nanosleep(32);
        }
        __threadfence();
    }
    __syncthreads();
}

// ---------------- kernels ---------------------------------------------------

__global__ void k_convert_dict(const float* __restrict__ dict) {
    size_t i = ((size_t)blockIdx.x * blockDim.x + threadIdx.x) * 4;
    float4 v = *(const float4*)(dict + i);
    *(uint32_t*)(g_dict_f8 + i) =
        f8x4(v.x * DSCALE, v.y * DSCALE, v.z * DSCALE, v.w * DSCALE);
}

__global__ void k_init(const float* __restrict__ x) {
    size_t i = ((size_t)blockIdx.x * blockDim.x + threadIdx.x) * 4;
    float4 v = *(const float4*)(x + i);
    *(float4*)(g_resid + i) = v;
    *(uint32_t*)(g_resid_f8 + i) =
        f8x4(v.x * RSCALE, v.y * RSCALE, v.z * RSCALE, v.w * RSCALE);
    if (blockIdx.x == 0 && threadIdx.x < BATCH) {
        g_rowmax[threadIdx.x] = 0u;
        g_cnt[threadIdx.x] = 0;
    }
}

// One MP iteration: scores -> reduce/max/superset-push -> rescore -> apply.
// grid 512 x 256, 51.2KB dynamic smem (4-stage padded pipeline), 4 CTAs/SM.
__global__ void __launch_bounds__(256, 4) k_iter(const float* __restrict__ dict) {
    extern __shared__ uint8_t dsm[];
    // sD stage b: dsm + b*SD_STAGE ; sR stage b: dsm + NSTAGE*SD_STAGE + b*SR_STAGE
    __shared__ float sred[8];
    __shared__ int   s_n;
    __shared__ int   s_idx[MAXC];
    __shared__ float s_w[MAXC];

    const int t = threadIdx.x;
    const int lane = t & 31, warp = t >> 5;
    const int bx = blockIdx.x;
    const int nt = bx & (NTILES - 1);
    const int kc = bx >> 5;
    const int r = bx & (BATCH - 1);
    const int slot = kc;

    const int atomBase = nt * ATILE;
    const int kBase = kc * KCHUNK;

    uint8_t* const sDp = dsm;
    uint8_t* const sRp = dsm + NSTAGE * SD_STAGE;

    // ================= Phase A: fp8 tensor-core scores =================
    {
        float c0[2][4] = {{0.f,0.f,0.f,0.f},{0.f,0.f,0.f,0.f}};
        float c1[2][4] = {{0.f,0.f,0.f,0.f},{0.f,0.f,0.f,0.f}};

        const int arow = lane & 15;
        const int acolsel = (lane & 16) ? 16 : 0;
        const int brow0 = warp * 16 + (lane & 7);
        const int brow1 = brow0 + 8;
        const int bcolsel = (lane & 8) ? 16 : 0;

        const int d0r = t >> 2, ds = t & 3;     // dict rows 0..63 (+64), seg 0..3
        const int rr = t >> 2, rs = t & 3;      // resid rows 0..31 (t<128)

        auto load_stage = [&](int buf, int kb) {
            const size_t gk = (size_t)(kBase + kb);
            uint8_t* sD = sDp + buf * SD_STAGE;
            uint8_t* sR = sRp + buf * SR_STAGE;
            cpa16(smem_u32(sD + d0r * SROW + ds * 16),
                  &g_dict_f8[(size_t)(atomBase + d0r) * DMODEL + gk + ds * 16]);
            cpa16(smem_u32(sD + (d0r + 64) * SROW + ds * 16),
                  &g_dict_f8[(size_t)(atomBase + d0r + 64) * DMODEL + gk + ds * 16]);
            if (t < 128)
                cpa16(smem_u32(sR + rr * SROW + rs * 16),
                      &g_resid_f8[(size_t)rr * DMODEL + gk + rs * 16]);
            cpa_commit();
        };

        load_stage(0, 0);
        load_stage(1, KB);
        load_stage(2, 2 * KB);

        for (int s = 0; s < NSTEPS; s++) {
            if (s + 3 < NSTEPS) load_stage((s + 3) & 3, (s + 3) * KB);
            else cpa_commit();
            cpa_wait3();
            __syncthreads();

            const int b = s & 3;
            const uint8_t* sD = sDp + b * SD_STAGE;
            const uint8_t* sR = sRp + b * SR_STAGE;
            #pragma unroll
            for (int ks = 0; ks < KB / 32; ks++) {
                uint32_t a0[4], a1[4], b0v[2], b1v[2];
                const int col = ks * 32;
                ldsm_x4(a0, smem_u32(sR + arow * SROW + col + acolsel));
                ldsm_x4(a1, smem_u32(sR + (16 + arow) * SROW + col + acolsel));
                ldsm_x2(b0v, smem_u32(sD + brow0 * SROW + col + bcolsel));
                ldsm_x2(b1v, smem_u32(sD + brow1 * SROW + col + bcolsel));
                mma16832(c0[0], a0, b0v);
                mma16832(c0[1], a1, b0v);
                mma16832(c1[0], a0, b1v);
                mma16832(c1[1], a1, b1v);
            }
            __syncthreads();
        }
        cpa_wait0();

        const int gr = lane >> 2;
        float* P = g_part + (size_t)kc * BATCH * ATOMS;
        #pragma unroll
        for (int beta = 0; beta < 2; beta++) {
            const int ac = atomBase + warp * 16 + beta * 8 + (lane & 3) * 2;
            const float (*c)[4] = beta ? c1 : c0;
            #pragma unroll
            for (int h = 0; h < 2; h++) {
                P[(size_t)(gr + h * 16 + 0) * ATOMS + ac]     = c[h][0];
                P[(size_t)(gr + h * 16 + 0) * ATOMS + ac + 1] = c[h][1];
                P[(size_t)(gr + h * 16 + 8) * ATOMS + ac]     = c[h][2];
                P[(size_t)(gr + h * 16 + 8) * ATOMS + ac + 1] = c[h][3];
            }
        }
    }

    gbar();   // all partials final (inherent full dependency)

    // ====== Phase B: reduce + slice max + atomicMax + superset push ====
    const int myAtom = slot * 256 + t;
    float myScore;
    {
        float s = 0.f;
        #pragma unroll
        for (int c = 0; c < KCHUNKS; c++)
            s += g_part[((size_t)c * BATCH + r) * ATOMS + myAtom];
        myScore = s * INV_S;
    }
    {
        float lmax = myScore;
        #pragma unroll
        for (int o = 16; o > 0; o >>= 1) lmax = fmaxf(lmax, __shfl_xor_sync(0xffffffffu, lmax, o));
        if (lane == 0) sred[warp] = lmax;
        __syncthreads();
        if (t == 0) {
            float mm = sred[0];
            #pragma unroll
            for (int i = 1; i < 8; i++) mm = fmaxf(mm, sred[i]);
            sred[0] = mm;
            atomicMax(&g_rowmax[r], fenc(mm));
        }
        __syncthreads();
    }
    // superset push vs slice-local max (guaranteed superset of global set)
    if (myScore > sred[0] - WINDOW) {
        int p = atomicAdd(&g_cnt[r], 1);
        if (p < MAXC) {
            g_cand[r * MAXC + p] = myAtom;
            g_csc[r * MAXC + p] = myScore;
        }
    }

    rowbar(r, 0);   // this row's max + superset list final

    // ====== Phase C: filter + sort (identical) + exact fp32 rescore =====
    if (t == 0) {
        const float thr = fdec(g_rowmax[r]) - WINDOW;
        const int cnt = min(g_cnt[r], MAXC);
        int n = 0;
        for (int i = 0; i < cnt; i++)
            if (g_csc[r * MAXC + i] > thr) s_idx[n++] = g_cand[r * MAXC + i];
        for (int i = 1; i < n; i++) {
            int v = s_idx[i], j = i - 1;
            while (j >= 0 && s_idx[j] > v) { s_idx[j + 1] = s_idx[j]; j--; }
            s_idx[j + 1] = v;
        }
        s_n = n;
    }
    __syncthreads();
    const int n = s_n;

    {
        const float* R = g_resid + (size_t)r * DMODEL;
        for (int j = slot; j < n; j += SLOTS) {
            const float* D = dict + (size_t)s_idx[j] * DMODEL;
            float acc = 0.f;
            #pragma unroll 4
            for (int d = t * 4; d < DMODEL; d += 1024) {
                const float4 rv = *(const float4*)(R + d);
                const float4 dv = *(const float4*)(D + d);
                acc += rv.x * dv.x + rv.y * dv.y + rv.z * dv.z + rv.w * dv.w;
            }
            #pragma unroll
            for (int o = 16; o > 0; o >>= 1) acc += __shfl_xor_sync(0xffffffffu, acc, o);
            if (lane == 0) sred[warp] = acc;
            __syncthreads();
            if (t == 0) {
                float s = 0.f;
                #pragma unroll
                for (int i = 0; i < 8; i++) s += sred[i];
                g_ex[r * MAXC + j] = s;
            }
            __syncthreads();
        }
    }

    rowbar(r, 1);   // this row's exact scores final

    // ================= Phase D: softmax + apply ========================
    if (t == 0) {
        float em = -1e30f;
        for (int j = 0; j < n; j++) em = fmaxf(em, g_ex[r * MAXC + j]);
        float den = 0.f;
        for (int j = 0; j < n; j++) {
            const float wv = expf((g_ex[r * MAXC + j] - em) / TEMP);
            s_w[j] = wv; den += wv;
        }
        const float inv = 1.f / den;
        for (int j = 0; j < n; j++) s_w[j] *= inv;
    }
    __syncthreads();

    {
        const int col = slot * 1024 + t * 4;
        const size_t base = (size_t)r * DMODEL + col;
        float4 v = *(const float4*)(g_resid + base);
        for (int j = 0; j < n; j++) {
            const float wj = s_w[j];
            const float4 dv = *(const float4*)(dict + (size_t)s_idx[j] * DMODEL + col);
            v.x -= wj * dv.x; v.y -= wj * dv.y; v.z -= wj * dv.z; v.w -= wj * dv.w;
        }
        *(float4*)(g_resid + base) = v;
        *(uint32_t*)(g_resid_f8 + base) =
            f8x4(v.x * RSCALE, v.y * RSCALE, v.z * RSCALE, v.w * RSCALE);
    }

    if (slot == 0 && t == 0) {
        g_cnt[r] = 0;
        g_rowmax[r] = 0u;
    }
}

// Fused epilogue: copy residual to out AND per-block square-sums.
__global__ void k_epilogue(float* out, int out_size) {
    __shared__ float s[256];
    const int b = blockIdx.x, t = threadIdx.x;
    const int off = (out_size > NRES) ? 1 : 0;
    const size_t base = (size_t)b * 1024;
    float acc = 0.f;
    #pragma unroll
    for (int i = 0; i < 4; i++) {
        const size_t idx = base + t + i * 256;
        const float v = g_resid[idx];
        out[off + idx] = v;
        acc += v * v;
    }
    s[t] = acc; __syncthreads();
    for (int o = 128; o > 0; o >>= 1) { if (t < o) s[t] += s[t + o]; __syncthreads(); }
    if (t == 0) g_lpart[b] = s[0];
}

__global__ void k_finalize(float* out, int out_size) {
    __shared__ float s[512];
    const int t = threadIdx.x;
    s[t] = g_lpart[t]; __syncthreads();
    for (int o = 256; o > 0; o >>= 1) { if (t < o) s[t] += s[t + o]; __syncthreads(); }
    if (t == 0 && out_size > NRES) out[0] = s[0] / (float)NRES;
}

// ---------------- launch ----------------------------------------------------
extern "C" void kernel_launch(void* const* d_in, const int* in_sizes, int n_in,
                              void* d_out, int out_size) {
    const float* x = nullptr;
    const float* dict = nullptr;
    for (int i = 0; i < n_in; i++) {
        if (in_sizes[i] == NRES) x = (const float*)d_in[i];
        else if (in_sizes[i] == ATOMS * DMODEL) dict = (const float*)d_in[i];
    }
    float* out = (float*)d_out;

    // 51.2KB dynamic smem opt-in (host attribute set; capture-legal, proven R13)
    cudaFuncSetAttribute(k_iter, cudaFuncAttributeMaxDynamicSharedMemorySize, 57344);

    k_convert_dict<<<65536, 256>>>(dict);
    k_init<<<512, 256>>>(x);

    for (int it = 0; it < ITERS; it++)
        k_iter<<<GRID_I, 256, DSMEM_BYTES>>>(dict);

    k_epilogue<<<512, 256>>>(out, out_size);
    k_finalize<<<1, 512>>>(out, out_size);
}